// round 1
// baseline (speedup 1.0000x reference)
#include <cuda_runtime.h>
#include <cuda_bf16.h>
#include <stdint.h>

#define TOKENS 8192
#define IN_F   4096
#define OUT_F  4096
#define RNK    16

// ---------------- scratch (no allocs allowed) ----------------
__device__ float g_S[256];              // S = lora_A @ lora_A^T   [16x16]
__device__ float g_C[256];              // C = lora_B^T @ lora_B   [16x16]
__device__ float g_Qs[256];             // alpha * Q5              [16x16]
__device__ float g_Z[TOKENS * RNK];     // Z = (x A^T) (alpha Q5)^T  [8192x16]

// ---------------- K0: zero accumulators ----------------
__global__ void k_zero() {
    int t = threadIdx.x;
    g_S[t] = 0.f;
    g_C[t] = 0.f;
}

// ---------------- K1: S and C (16x16 gram matrices) ----------------
// grid 16 blocks, each handles a k-chunk of 256, atomicAdd partials.
__global__ void k_sc(const float* __restrict__ lA, const float* __restrict__ lB) {
    int t = threadIdx.x;
    int i = t >> 4, j = t & 15;
    int k0 = blockIdx.x * 256;

    const float4* Ai = (const float4*)(lA + (size_t)i * IN_F);
    const float4* Aj = (const float4*)(lA + (size_t)j * IN_F);
    float s = 0.f;
#pragma unroll 8
    for (int k4 = k0 / 4; k4 < k0 / 4 + 64; k4++) {
        float4 a = Ai[k4], b = Aj[k4];
        s += a.x * b.x + a.y * b.y + a.z * b.z + a.w * b.w;
    }
    float c = 0.f;
#pragma unroll 4
    for (int k = k0; k < k0 + 256; k++) {
        c += lB[(size_t)k * RNK + i] * lB[(size_t)k * RNK + j];
    }
    atomicAdd(&g_S[t], s);
    atomicAdd(&g_C[t], c);
}

// ---------------- K2: Newton-Schulz in the rank-16 space ----------------
// X_k = B Q_k A ; Q_0 = I/(alpha+eps) ; R_k = Q_k^T C Q_k ;
// P = aI + b(S R) + c(S R)^2 ; Q <- Q P ; R <- P^T R P.  g_Qs = alpha * Q_5.
__global__ void k_ns() {
    __shared__ float S[256], C[256], Q[256], Rm[256], T1[256], T2[256], P[256], W2[256];
    int t = threadIdx.x, i = t >> 4, j = t & 15;

    S[t] = g_S[t];
    C[t] = g_C[t];
    __syncthreads();

    // trace(S*C) = ||G||_F^2
    W2[t] = S[i * 16 + j] * C[j * 16 + i];
    __syncthreads();
    for (int s = 128; s; s >>= 1) {
        if (t < s) W2[t] += W2[t + s];
        __syncthreads();
    }
    float alpha = sqrtf(W2[0]);
    float nrm = alpha + 1e-7f;

    Q[t]  = (i == j) ? (1.f / nrm) : 0.f;
    Rm[t] = C[t] / (nrm * nrm);
    __syncthreads();

    const float ca = 3.4445f, cb = -4.775f, cc = 2.0315f;
    for (int step = 0; step < 5; step++) {
        float acc = 0.f;
#pragma unroll
        for (int k = 0; k < 16; k++) acc += S[i * 16 + k] * Rm[k * 16 + j];
        T1[t] = acc;
        __syncthreads();

        acc = 0.f;
#pragma unroll
        for (int k = 0; k < 16; k++) acc += T1[i * 16 + k] * T1[k * 16 + j];
        T2[t] = acc;
        __syncthreads();

        P[t] = cc * T2[t] + cb * T1[t] + ((i == j) ? ca : 0.f);
        __syncthreads();

        // Q <- Q * P
        acc = 0.f;
#pragma unroll
        for (int k = 0; k < 16; k++) acc += Q[i * 16 + k] * P[k * 16 + j];
        W2[t] = acc;
        __syncthreads();
        Q[t] = W2[t];  // own element only, no cross-thread hazard

        // W2 <- Rm * P
        acc = 0.f;
#pragma unroll
        for (int k = 0; k < 16; k++) acc += Rm[i * 16 + k] * P[k * 16 + j];
        W2[t] = acc;
        __syncthreads();

        // Rm <- P^T * W2
        acc = 0.f;
#pragma unroll
        for (int k = 0; k < 16; k++) acc += P[k * 16 + i] * W2[k * 16 + j];
        T1[t] = acc;
        __syncthreads();
        Rm[t] = T1[t];
        __syncthreads();
    }
    g_Qs[t] = alpha * Q[t];
}

// ---------------- K3: U = x @ lora_A^T, then Z = U @ Qs^T ----------------
// One warp per token row. Memory-bound: one pass over x.
__global__ void k_u(const float* __restrict__ x, const float* __restrict__ lA) {
    int lane = threadIdx.x & 31, warp = threadIdx.x >> 5;
    int row = blockIdx.x * 8 + warp;
    const float4* xr = (const float4*)(x + (size_t)row * IN_F);

    float acc[16];
#pragma unroll
    for (int r = 0; r < 16; r++) acc[r] = 0.f;

    for (int it = 0; it < IN_F / 128; it++) {
        int k4 = lane + 32 * it;
        float4 xv = xr[k4];
#pragma unroll
        for (int r = 0; r < 16; r++) {
            float4 av = ((const float4*)(lA + (size_t)r * IN_F))[k4];
            acc[r] += xv.x * av.x + xv.y * av.y + xv.z * av.z + xv.w * av.w;
        }
    }
#pragma unroll
    for (int r = 0; r < 16; r++) {
#pragma unroll
        for (int off = 16; off; off >>= 1)
            acc[r] += __shfl_xor_sync(0xffffffffu, acc[r], off);
    }
    if (lane < 16) {
        float z = 0.f;
#pragma unroll
        for (int s = 0; s < 16; s++) z += acc[s] * g_Qs[lane * 16 + s];
        g_Z[(size_t)row * RNK + lane] = z;
    }
}

// ---------------- K4: main GEMM (bf16 split-3) + bias + lora epilogue ----------------
// out = x @ W^T + bias + Z @ lora_B^T
// Block tile 128x128, K-tile 32. 8 warps (2x4), warp tile 64x32.
// fp32 -> (bf16 hi, bf16 lo); acc += xh*Wh + xh*Wl + xl*Wh via mma.m16n8k16.

#define LDP 40  // smem row stride in bf16 elems (conflict-free for frag loads)

__device__ __forceinline__ void mma16816(float* c, const uint32_t* a, const uint32_t* b) {
    asm volatile(
        "mma.sync.aligned.m16n8k16.row.col.f32.bf16.bf16.f32 "
        "{%0,%1,%2,%3}, {%4,%5,%6,%7}, {%8,%9}, {%0,%1,%2,%3};\n"
        : "+f"(c[0]), "+f"(c[1]), "+f"(c[2]), "+f"(c[3])
        : "r"(a[0]), "r"(a[1]), "r"(a[2]), "r"(a[3]), "r"(b[0]), "r"(b[1]));
}

__device__ __forceinline__ void cvt_store(float4 v, __nv_bfloat16* sh, __nv_bfloat16* sl, int off) {
    __nv_bfloat16 h0 = __float2bfloat16(v.x);
    __nv_bfloat16 h1 = __float2bfloat16(v.y);
    __nv_bfloat16 h2 = __float2bfloat16(v.z);
    __nv_bfloat16 h3 = __float2bfloat16(v.w);
    __nv_bfloat162 p0; p0.x = h0; p0.y = h1;
    __nv_bfloat162 p1; p1.x = h2; p1.y = h3;
    *(__nv_bfloat162*)(sh + off)     = p0;
    *(__nv_bfloat162*)(sh + off + 2) = p1;
    __nv_bfloat16 l0 = __float2bfloat16(v.x - __bfloat162float(h0));
    __nv_bfloat16 l1 = __float2bfloat16(v.y - __bfloat162float(h1));
    __nv_bfloat16 l2 = __float2bfloat16(v.z - __bfloat162float(h2));
    __nv_bfloat16 l3 = __float2bfloat16(v.w - __bfloat162float(h3));
    __nv_bfloat162 q0; q0.x = l0; q0.y = l1;
    __nv_bfloat162 q1; q1.x = l2; q1.y = l3;
    *(__nv_bfloat162*)(sl + off)     = q0;
    *(__nv_bfloat162*)(sl + off + 2) = q1;
}

__device__ __forceinline__ void mma_step(
    const __nv_bfloat16* sXh, const __nv_bfloat16* sXl,
    const __nv_bfloat16* sWh, const __nv_bfloat16* sWl,
    int ks, int wm, int wn, int g, int tg, float acc[4][4][4])
{
    uint32_t ah[4][4], al[4][4], bh[4][2], bl[4][2];
#pragma unroll
    for (int mt = 0; mt < 4; mt++) {
        int o0 = (wm * 64 + mt * 16 + g) * LDP + ks + tg * 2;
        int o1 = o0 + 8 * LDP;
        ah[mt][0] = *(const uint32_t*)(sXh + o0);
        ah[mt][1] = *(const uint32_t*)(sXh + o1);
        ah[mt][2] = *(const uint32_t*)(sXh + o0 + 8);
        ah[mt][3] = *(const uint32_t*)(sXh + o1 + 8);
        al[mt][0] = *(const uint32_t*)(sXl + o0);
        al[mt][1] = *(const uint32_t*)(sXl + o1);
        al[mt][2] = *(const uint32_t*)(sXl + o0 + 8);
        al[mt][3] = *(const uint32_t*)(sXl + o1 + 8);
    }
#pragma unroll
    for (int nt = 0; nt < 4; nt++) {
        int ob = (wn * 32 + nt * 8 + g) * LDP + ks + tg * 2;
        bh[nt][0] = *(const uint32_t*)(sWh + ob);
        bh[nt][1] = *(const uint32_t*)(sWh + ob + 8);
        bl[nt][0] = *(const uint32_t*)(sWl + ob);
        bl[nt][1] = *(const uint32_t*)(sWl + ob + 8);
    }
#pragma unroll
    for (int mt = 0; mt < 4; mt++) {
#pragma unroll
        for (int nt = 0; nt < 4; nt++) {
            mma16816(acc[mt][nt], ah[mt], bh[nt]);  // hi*hi
            mma16816(acc[mt][nt], ah[mt], bl[nt]);  // hi*lo
            mma16816(acc[mt][nt], al[mt], bh[nt]);  // lo*hi
        }
    }
}

__global__ void __launch_bounds__(256, 1)
k_gemm(const float* __restrict__ x, const float* __restrict__ W,
       const float* __restrict__ bias, const float* __restrict__ lB,
       float* __restrict__ out)
{
    __shared__ __nv_bfloat16 smem[4 * 128 * LDP];
    __nv_bfloat16* sXh = smem;
    __nv_bfloat16* sXl = smem + 128 * LDP;
    __nv_bfloat16* sWh = smem + 2 * 128 * LDP;
    __nv_bfloat16* sWl = smem + 3 * 128 * LDP;

    int tid  = threadIdx.x;
    int warp = tid >> 5, lane = tid & 31;
    int wm = warp & 1, wn = warp >> 1;      // 2 x 4 warp grid
    int g  = lane >> 2, tg = lane & 3;

    int m0 = blockIdx.y * 128;
    int n0 = blockIdx.x * 128;

    float acc[4][4][4];
#pragma unroll
    for (int a = 0; a < 4; a++)
#pragma unroll
        for (int b = 0; b < 4; b++)
#pragma unroll
            for (int c = 0; c < 4; c++) acc[a][b][c] = 0.f;

    for (int kb = 0; kb < IN_F / 32; kb++) {
        int k0 = kb * 32;
        // load + convert x and W tiles (128x32 each)
#pragma unroll
        for (int r = 0; r < 4; r++) {
            int idx = tid + r * 256;          // 0..1023
            int row = idx >> 3;               // 0..127
            int c4  = idx & 7;                // 0..7 (float4 within 32 cols)
            float4 xv = *(const float4*)&x[(size_t)(m0 + row) * IN_F + k0 + c4 * 4];
            cvt_store(xv, sXh, sXl, row * LDP + c4 * 4);
            float4 wv = *(const float4*)&W[(size_t)(n0 + row) * IN_F + k0 + c4 * 4];
            cvt_store(wv, sWh, sWl, row * LDP + c4 * 4);
        }
        __syncthreads();
        mma_step(sXh, sXl, sWh, sWl, 0,  wm, wn, g, tg, acc);
        mma_step(sXh, sXl, sWh, sWl, 16, wm, wn, g, tg, acc);
        __syncthreads();
    }

    // lora extension: one extra K=16 step with A-tile = Z, B-tile = lora_B
#pragma unroll
    for (int r = 0; r < 2; r++) {
        int idx = tid + r * 256;              // 0..511
        int row = idx >> 2;                   // 0..127
        int c4  = idx & 3;                    // 0..3 (float4 within 16 cols)
        float4 zv = *(const float4*)&g_Z[(size_t)(m0 + row) * RNK + c4 * 4];
        cvt_store(zv, sXh, sXl, row * LDP + c4 * 4);
        float4 bv = *(const float4*)&lB[(size_t)(n0 + row) * RNK + c4 * 4];
        cvt_store(bv, sWh, sWl, row * LDP + c4 * 4);
    }
    __syncthreads();
    mma_step(sXh, sXl, sWh, sWl, 0, wm, wn, g, tg, acc);

    // epilogue: + bias, store
#pragma unroll
    for (int nt = 0; nt < 4; nt++) {
        int c = n0 + wn * 32 + nt * 8 + tg * 2;
        float b0 = __ldg(&bias[c]);
        float b1 = __ldg(&bias[c + 1]);
#pragma unroll
        for (int mt = 0; mt < 4; mt++) {
            int r0 = m0 + wm * 64 + mt * 16 + g;
            float2 v0, v1;
            v0.x = acc[mt][nt][0] + b0;
            v0.y = acc[mt][nt][1] + b1;
            v1.x = acc[mt][nt][2] + b0;
            v1.y = acc[mt][nt][3] + b1;
            *(float2*)&out[(size_t)r0 * OUT_F + c]       = v0;
            *(float2*)&out[(size_t)(r0 + 8) * OUT_F + c] = v1;
        }
    }
}

// ---------------- launch ----------------
extern "C" void kernel_launch(void* const* d_in, const int* in_sizes, int n_in,
                              void* d_out, int out_size) {
    const float* x    = (const float*)d_in[0];
    const float* W    = (const float*)d_in[1];
    const float* bias = (const float*)d_in[2];
    const float* lA   = (const float*)d_in[3];
    const float* lB   = (const float*)d_in[4];
    float* out = (float*)d_out;

    k_zero<<<1, 256>>>();
    k_sc<<<16, 256>>>(lA, lB);
    k_ns<<<1, 256>>>();
    k_u<<<TOKENS / 8, 256>>>(x, lA);
    dim3 grid(OUT_F / 128, TOKENS / 128);
    k_gemm<<<grid, 256>>>(x, W, bias, lB, out);
}

// round 3
// speedup vs baseline: 1.3795x; 1.3795x over previous
#include <cuda_runtime.h>
#include <cuda_bf16.h>
#include <stdint.h>

#define TOKENS 8192
#define IN_F   4096
#define OUT_F  4096
#define RNK    16

// ================= device scratch (no allocs allowed) =================
__device__ float g_S[256];
__device__ float g_C[256];
__device__ float g_Qs[256];                         // alpha * Q5
__device__ float g_Aq[RNK * IN_F];                  // (alpha Q5) @ lora_A
__device__ __align__(1024) __nv_bfloat16 g_Xh[(size_t)TOKENS * IN_F];
__device__ __align__(1024) __nv_bfloat16 g_Xl[(size_t)TOKENS * IN_F];
__device__ __align__(1024) __nv_bfloat16 g_Wh[(size_t)OUT_F * IN_F];
__device__ __align__(1024) __nv_bfloat16 g_Wl[(size_t)OUT_F * IN_F];

// ================= K0/K1/K2: alpha*Q5 in rank-16 space (validated R1) ==========
__global__ void k_zero() { int t = threadIdx.x; g_S[t] = 0.f; g_C[t] = 0.f; }

__global__ void k_sc(const float* __restrict__ lA, const float* __restrict__ lB) {
    int t = threadIdx.x, i = t >> 4, j = t & 15;
    int k0 = blockIdx.x * 256;
    const float4* Ai = (const float4*)(lA + (size_t)i * IN_F);
    const float4* Aj = (const float4*)(lA + (size_t)j * IN_F);
    float s = 0.f;
#pragma unroll 8
    for (int k4 = k0 / 4; k4 < k0 / 4 + 64; k4++) {
        float4 a = Ai[k4], b = Aj[k4];
        s += a.x * b.x + a.y * b.y + a.z * b.z + a.w * b.w;
    }
    float c = 0.f;
#pragma unroll 4
    for (int k = k0; k < k0 + 256; k++)
        c += lB[(size_t)k * RNK + i] * lB[(size_t)k * RNK + j];
    atomicAdd(&g_S[t], s);
    atomicAdd(&g_C[t], c);
}

__global__ void k_ns() {
    __shared__ float S[256], C[256], Q[256], Rm[256], T1[256], T2[256], P[256], W2[256];
    int t = threadIdx.x, i = t >> 4, j = t & 15;
    S[t] = g_S[t]; C[t] = g_C[t];
    __syncthreads();
    W2[t] = S[i * 16 + j] * C[j * 16 + i];
    __syncthreads();
    for (int s = 128; s; s >>= 1) { if (t < s) W2[t] += W2[t + s]; __syncthreads(); }
    float alpha = sqrtf(W2[0]);
    float nrm = alpha + 1e-7f;
    Q[t] = (i == j) ? (1.f / nrm) : 0.f;
    Rm[t] = C[t] / (nrm * nrm);
    __syncthreads();
    const float ca = 3.4445f, cb = -4.775f, cc = 2.0315f;
    for (int step = 0; step < 5; step++) {
        float acc = 0.f;
#pragma unroll
        for (int k = 0; k < 16; k++) acc += S[i * 16 + k] * Rm[k * 16 + j];
        T1[t] = acc; __syncthreads();
        acc = 0.f;
#pragma unroll
        for (int k = 0; k < 16; k++) acc += T1[i * 16 + k] * T1[k * 16 + j];
        T2[t] = acc; __syncthreads();
        P[t] = cc * T2[t] + cb * T1[t] + ((i == j) ? ca : 0.f);
        __syncthreads();
        acc = 0.f;
#pragma unroll
        for (int k = 0; k < 16; k++) acc += Q[i * 16 + k] * P[k * 16 + j];
        W2[t] = acc; __syncthreads(); Q[t] = W2[t];
        acc = 0.f;
#pragma unroll
        for (int k = 0; k < 16; k++) acc += Rm[i * 16 + k] * P[k * 16 + j];
        W2[t] = acc; __syncthreads();
        acc = 0.f;
#pragma unroll
        for (int k = 0; k < 16; k++) acc += P[k * 16 + i] * W2[k * 16 + j];
        T1[t] = acc; __syncthreads(); Rm[t] = T1[t]; __syncthreads();
    }
    g_Qs[t] = alpha * Q[t];
}

// ================= K3: Aq = (alpha Q5) @ lora_A  [16 x 4096] =================
__global__ void k_aq(const float* __restrict__ lA) {
    int j = blockIdx.x * 256 + threadIdx.x;
    float a[16];
#pragma unroll
    for (int s = 0; s < 16; s++) a[s] = lA[(size_t)s * IN_F + j];
#pragma unroll
    for (int r = 0; r < 16; r++) {
        float acc = 0.f;
#pragma unroll
        for (int s = 0; s < 16; s++) acc += g_Qs[r * 16 + s] * a[s];
        g_Aq[(size_t)r * IN_F + j] = acc;
    }
}

// ============ K4: W' = W + lB @ Aq; split to bf16 hi/lo =====================
__global__ void k_wprep(const float* __restrict__ W, const float* __restrict__ lB) {
    __shared__ float sAq[16 * 256];
    __shared__ float sB[64 * 16];
    int tid = threadIdx.x;
    int c0 = blockIdx.x * 256, i0 = blockIdx.y * 64;
#pragma unroll
    for (int q = 0; q < 16; q++) {
        int i = tid + 256 * q;
        sAq[i] = g_Aq[(size_t)(i >> 8) * IN_F + c0 + (i & 255)];
    }
#pragma unroll
    for (int q = 0; q < 4; q++) {
        int i = tid + 256 * q;
        sB[i] = lB[(size_t)(i0 + (i >> 4)) * RNK + (i & 15)];
    }
    __syncthreads();
    int col = c0 + tid;
    float aq[16];
#pragma unroll
    for (int r = 0; r < 16; r++) aq[r] = sAq[r * 256 + tid];
    for (int ir = 0; ir < 64; ir++) {
        size_t off = (size_t)(i0 + ir) * IN_F + col;
        float acc = W[off];
#pragma unroll
        for (int r = 0; r < 16; r++) acc += sB[ir * 16 + r] * aq[r];
        __nv_bfloat16 h = __float2bfloat16(acc);
        g_Wh[off] = h;
        g_Wl[off] = __float2bfloat16(acc - __bfloat162float(h));
    }
}

// ================= K5: split x into bf16 hi/lo =================
__global__ void k_xsplit(const float* __restrict__ x) {
    size_t i = (size_t)blockIdx.x * 256 + threadIdx.x;   // float4 index
    float4 v = ((const float4*)x)[i];
    __nv_bfloat16 h0 = __float2bfloat16(v.x), h1 = __float2bfloat16(v.y);
    __nv_bfloat16 h2 = __float2bfloat16(v.z), h3 = __float2bfloat16(v.w);
    __nv_bfloat162 a; a.x = h0; a.y = h1;
    __nv_bfloat162 b; b.x = h2; b.y = h3;
    ((__nv_bfloat162*)g_Xh)[i * 2]     = a;
    ((__nv_bfloat162*)g_Xh)[i * 2 + 1] = b;
    __nv_bfloat162 c, d;
    c.x = __float2bfloat16(v.x - __bfloat162float(h0));
    c.y = __float2bfloat16(v.y - __bfloat162float(h1));
    d.x = __float2bfloat16(v.z - __bfloat162float(h2));
    d.y = __float2bfloat16(v.w - __bfloat162float(h3));
    ((__nv_bfloat162*)g_Xl)[i * 2]     = c;
    ((__nv_bfloat162*)g_Xl)[i * 2 + 1] = d;
}

// ================= K6: mma.sync GEMM, 128x128 tile, 4-stage cp.async =========
// out = [Xh+Xl] @ [Wh+Wl]^T + bias  (3 terms: XhWh + XhWl + XlWh)
#define LDP   40                      // smem row stride (bf16), conflict-free
#define NSTG  4
#define KSTG  32
#define TILE_B (128 * LDP * 2)        // 10240 B per tile
#define STAGE_B (4 * TILE_B)          // 40960 B per stage (Xh,Xl,Wh,Wl)

#define CP_ASYNC16(dst, src) \
    asm volatile("cp.async.cg.shared.global [%0], [%1], 16;" :: "r"(dst), "l"(src))
#define CP_COMMIT() asm volatile("cp.async.commit_group;" ::: "memory")
#define CP_WAIT2()  asm volatile("cp.async.wait_group 2;" ::: "memory")

__device__ __forceinline__ uint32_t smem_u32(const void* p) {
    uint32_t a;
    asm("{ .reg .u64 t; cvta.to.shared.u64 t, %1; cvt.u32.u64 %0, t; }" : "=r"(a) : "l"(p));
    return a;
}

__device__ __forceinline__ void mma16816(float* c, const uint32_t* a, const uint32_t* b) {
    asm volatile(
        "mma.sync.aligned.m16n8k16.row.col.f32.bf16.bf16.f32 "
        "{%0,%1,%2,%3}, {%4,%5,%6,%7}, {%8,%9}, {%0,%1,%2,%3};\n"
        : "+f"(c[0]), "+f"(c[1]), "+f"(c[2]), "+f"(c[3])
        : "r"(a[0]), "r"(a[1]), "r"(a[2]), "r"(a[3]), "r"(b[0]), "r"(b[1]));
}

__device__ __forceinline__ void mma_step(
    const __nv_bfloat16* sXh, const __nv_bfloat16* sXl,
    const __nv_bfloat16* sWh, const __nv_bfloat16* sWl,
    int ks, int wm, int wn, int g, int tg, float acc[4][4][4])
{
    uint32_t ah[4][4], al[4][4], bh[4][2], bl[4][2];
#pragma unroll
    for (int mt = 0; mt < 4; mt++) {
        int o0 = (wm * 64 + mt * 16 + g) * LDP + ks + tg * 2;
        int o1 = o0 + 8 * LDP;
        ah[mt][0] = *(const uint32_t*)(sXh + o0);
        ah[mt][1] = *(const uint32_t*)(sXh + o1);
        ah[mt][2] = *(const uint32_t*)(sXh + o0 + 8);
        ah[mt][3] = *(const uint32_t*)(sXh + o1 + 8);
        al[mt][0] = *(const uint32_t*)(sXl + o0);
        al[mt][1] = *(const uint32_t*)(sXl + o1);
        al[mt][2] = *(const uint32_t*)(sXl + o0 + 8);
        al[mt][3] = *(const uint32_t*)(sXl + o1 + 8);
    }
#pragma unroll
    for (int nt = 0; nt < 4; nt++) {
        int ob = (wn * 32 + nt * 8 + g) * LDP + ks + tg * 2;
        bh[nt][0] = *(const uint32_t*)(sWh + ob);
        bh[nt][1] = *(const uint32_t*)(sWh + ob + 8);
        bl[nt][0] = *(const uint32_t*)(sWl + ob);
        bl[nt][1] = *(const uint32_t*)(sWl + ob + 8);
    }
#pragma unroll
    for (int mt = 0; mt < 4; mt++) {
#pragma unroll
        for (int nt = 0; nt < 4; nt++) {
            mma16816(acc[mt][nt], ah[mt], bh[nt]);
            mma16816(acc[mt][nt], ah[mt], bl[nt]);
            mma16816(acc[mt][nt], al[mt], bh[nt]);
        }
    }
}

__global__ void __launch_bounds__(256, 1)
k_gemm(const float* __restrict__ bias, float* __restrict__ out)
{
    extern __shared__ __align__(128) char dsm[];
    uint32_t sbase = smem_u32(dsm);

    int tid  = threadIdx.x;
    int warp = tid >> 5, lane = tid & 31;
    int wm = warp & 1, wn = warp >> 1;
    int g  = lane >> 2, tg = lane & 3;

    int bx = blockIdx.x;
    int m0 = (bx >> 5) * 128;
    int n0 = (bx & 31) * 128;

    // per-thread cp.async assignments: 8 chunks of 16B per stage
    const char* gsrc[8];
    uint32_t sdst[8];
    {
        const char* basep[4] = { (const char*)g_Xh, (const char*)g_Xl,
                                 (const char*)g_Wh, (const char*)g_Wl };
#pragma unroll
        for (int j = 0; j < 8; j++) {
            int idx  = tid + 256 * j;       // 0..2047
            int tile = idx >> 9;            // 0..3
            int c    = idx & 511;
            int row  = c >> 2;              // 0..127
            int c4   = c & 3;               // 0..3 (16B chunk in 64B row)
            int grow = (tile < 2 ? m0 : n0) + row;
            gsrc[j] = basep[tile] + ((size_t)grow * IN_F + c4 * 8) * 2;
            sdst[j] = sbase + tile * TILE_B + row * (LDP * 2) + c4 * 16;
        }
    }

    float acc[4][4][4];
#pragma unroll
    for (int a = 0; a < 4; a++)
#pragma unroll
        for (int b = 0; b < 4; b++)
#pragma unroll
            for (int c = 0; c < 4; c++) acc[a][b][c] = 0.f;

    const int NKB = IN_F / KSTG;   // 128

    // prologue: stages 0..2
#pragma unroll
    for (int s = 0; s < NSTG - 1; s++) {
        uint32_t so = s * STAGE_B;
        long ko = (long)s * (KSTG * 2);
#pragma unroll
        for (int j = 0; j < 8; j++) CP_ASYNC16(sdst[j] + so, gsrc[j] + ko);
        CP_COMMIT();
    }

    for (int kb = 0; kb < NKB; kb++) {
        CP_WAIT2();
        __syncthreads();

        // issue loads for stage kb+3
        if (kb + NSTG - 1 < NKB) {
            uint32_t so = ((kb + NSTG - 1) & (NSTG - 1)) * STAGE_B;
            long ko = (long)(kb + NSTG - 1) * (KSTG * 2);
#pragma unroll
            for (int j = 0; j < 8; j++) CP_ASYNC16(sdst[j] + so, gsrc[j] + ko);
        }
        CP_COMMIT();   // commit every iter so wait_group count stays aligned

        const char* stg = dsm + (kb & (NSTG - 1)) * STAGE_B;
        const __nv_bfloat16* sXh = (const __nv_bfloat16*)(stg);
        const __nv_bfloat16* sXl = (const __nv_bfloat16*)(stg + TILE_B);
        const __nv_bfloat16* sWh = (const __nv_bfloat16*)(stg + 2 * TILE_B);
        const __nv_bfloat16* sWl = (const __nv_bfloat16*)(stg + 3 * TILE_B);
        mma_step(sXh, sXl, sWh, sWl, 0,  wm, wn, g, tg, acc);
        mma_step(sXh, sXl, sWh, sWl, 16, wm, wn, g, tg, acc);
        __syncthreads();
    }

    // epilogue: + bias, store fp32
#pragma unroll
    for (int nt = 0; nt < 4; nt++) {
        int c = n0 + wn * 32 + nt * 8 + tg * 2;
        float b0 = __ldg(&bias[c]);
        float b1 = __ldg(&bias[c + 1]);
#pragma unroll
        for (int mt = 0; mt < 4; mt++) {
            int r0 = m0 + wm * 64 + mt * 16 + g;
            float2 v0, v1;
            v0.x = acc[mt][nt][0] + b0;
            v0.y = acc[mt][nt][1] + b1;
            v1.x = acc[mt][nt][2] + b0;
            v1.y = acc[mt][nt][3] + b1;
            *(float2*)&out[(size_t)r0 * OUT_F + c]       = v0;
            *(float2*)&out[(size_t)(r0 + 8) * OUT_F + c] = v1;
        }
    }
}

// ================= launch =================
extern "C" void kernel_launch(void* const* d_in, const int* in_sizes, int n_in,
                              void* d_out, int out_size) {
    const float* x    = (const float*)d_in[0];
    const float* W    = (const float*)d_in[1];
    const float* bias = (const float*)d_in[2];
    const float* lA   = (const float*)d_in[3];
    const float* lB   = (const float*)d_in[4];
    float* out = (float*)d_out;

    k_zero<<<1, 256>>>();
    k_sc<<<16, 256>>>(lA, lB);
    k_ns<<<1, 256>>>();
    k_aq<<<16, 256>>>(lA);
    {
        dim3 g(IN_F / 256, OUT_F / 64);
        k_wprep<<<g, 256>>>(W, lB);
    }
    k_xsplit<<<(TOKENS * (IN_F / 4)) / 256, 256>>>(x);

    static int smem_set = 0;
    int smem_sz = NSTG * STAGE_B;   // 163840
    if (!smem_set) {
        cudaFuncSetAttribute(k_gemm, cudaFuncAttributeMaxDynamicSharedMemorySize, smem_sz);
        smem_set = 1;
    }
    int nblocks = (TOKENS / 128) * (OUT_F / 128);   // 2048
    k_gemm<<<nblocks, 256, smem_sz>>>(bias, out);
}